// round 3
// baseline (speedup 1.0000x reference)
#include <cuda_runtime.h>
#include <cstdint>
#include <math.h>

// ConvDBN: 2-layer convolutional RBM with stochastic multinomial pooling.
// Conv accumulation is a strict sequential fp32 FMA chain per output in
// k = (kh, kw, c_in) ascending order (c innermost) to bit-match XLA:CPU's
// Eigen conv (NHWC/HWIO im2col + GEBP single-chain reduction).

#define CP 100  // padded channel stride for L2 smem window

__device__ float g_h1[64 * 30 * 30 * 96];   // h1 in NHWC: [b][h][w][c]
__device__ float g_w2t[49 * 192 * 96];      // W2 transposed: [kh*7+kw][c2][c]

// ---------------- Threefry-2x32 (JAX partitionable scheme) ----------------
__host__ __device__ __forceinline__ void tf2x32(uint32_t k0, uint32_t k1,
                                                uint32_t x0, uint32_t x1,
                                                uint32_t &o0, uint32_t &o1) {
  uint32_t ks2 = k0 ^ k1 ^ 0x1BD11BDAu;
  x0 += k0; x1 += k1;
#define TF_RND(r) { x0 += x1; x1 = (x1 << (r)) | (x1 >> (32 - (r))); x1 ^= x0; }
  TF_RND(13) TF_RND(15) TF_RND(26) TF_RND(6)
  x0 += k1;  x1 += ks2 + 1u;
  TF_RND(17) TF_RND(29) TF_RND(16) TF_RND(24)
  x0 += ks2; x1 += k0 + 2u;
  TF_RND(13) TF_RND(15) TF_RND(26) TF_RND(6)
  x0 += k0;  x1 += k1 + 3u;
  TF_RND(17) TF_RND(29) TF_RND(16) TF_RND(24)
  x0 += k1;  x1 += ks2 + 4u;
  TF_RND(13) TF_RND(15) TF_RND(26) TF_RND(6)
  x0 += ks2; x1 += k0 + 5u;
#undef TF_RND
  o0 = x0; o1 = x1;
}

__device__ __forceinline__ float gumbel_at(uint32_t k0, uint32_t k1, uint32_t idx) {
  uint32_t o0, o1;
  tf2x32(k0, k1, 0u, idx, o0, o1);
  uint32_t bits = o0 ^ o1;
  float f = __uint_as_float((bits >> 9) | 0x3F800000u) - 1.0f;    // [0,1)
  const float tiny = 1.1754943508222875e-38f;
  f = fmaxf(tiny, f + tiny);                                       // uniform(tiny, 1)
  return -logf(-logf(f));
}

// winner = argmax(log(p+1e-8)+g), first index wins ties; returns p[winner]
__device__ __forceinline__ float pool9(const float p[9], uint32_t k0, uint32_t k1,
                                       uint32_t base) {
  float best = -1e30f;
  int win = 0;
#pragma unroll
  for (int j = 0; j < 9; j++) {
    float m = logf(p[j] + 1e-8f) + gumbel_at(k0, k1, base + (uint32_t)j);
    if (m > best) { best = m; win = j; }
  }
  return p[win];
}

// ---------------- W2 transpose: [c2][c][kh][kw] -> [kk][c2][c] ----------------
__global__ void w2t_kernel(const float *__restrict__ w2) {
  int idx = blockIdx.x * 256 + threadIdx.x;   // 49*192*96 = 903168 exact
  int c = idx % 96;
  int t = idx / 96;
  int c2 = t % 192;
  int kk = t / 192;
  g_w2t[idx] = w2[(c2 * 96 + c) * 49 + kk];
}

// ---------------- Layer 1 ----------------
// grid (64, 12): (batch, group of 8 out-channels). 256 threads.
// Items: 8 ch x 900 pooled positions. Order per output: kh{ kw{ ci{ fma } } }.
__global__ void __launch_bounds__(256) l1_kernel(const float *__restrict__ x,
                                                 const float *__restrict__ w1,
                                                 const float *__restrict__ b1,
                                                 uint32_t k0, uint32_t k1) {
  extern __shared__ float sm[];
  float *xs = sm;            // 3*96*96 = 27648 floats
  float *ws = sm + 27648;    // 8*147 = 1176 floats
  const int b = blockIdx.x, cg = blockIdx.y;

  const float *xb = x + (size_t)b * 27648;
  for (int i = threadIdx.x; i < 27648 / 4; i += 256)
    ((float4 *)xs)[i] = ((const float4 *)xb)[i];
  for (int i = threadIdx.x; i < 1176; i += 256)
    ws[i] = w1[cg * 1176 + i];
  __syncthreads();

  for (int item = threadIdx.x; item < 7200; item += 256) {
    const int c_l = item / 900, pos = item - c_l * 900;
    const int hb = pos / 30, wb = pos - hb * 30;
    const int r0 = hb * 3, q0 = wb * 3;
    const float *wp = ws + c_l * 147;

    float acc[9];
#pragma unroll
    for (int j = 0; j < 9; j++) acc[j] = 0.0f;
    float v[3][3][9];  // [ci][row(dy)][col]

#pragma unroll
    for (int kh = 0; kh < 7; kh++) {
#pragma unroll
      for (int ci = 0; ci < 3; ci++) {
        if (kh == 0) {
#pragma unroll
          for (int dy = 0; dy < 3; dy++)
#pragma unroll
            for (int dx = 0; dx < 9; dx++)
              v[ci][dy][dx] = xs[(ci * 96 + r0 + dy) * 96 + q0 + dx];
        } else {
#pragma unroll
          for (int dx = 0; dx < 9; dx++) {
            v[ci][0][dx] = v[ci][1][dx];
            v[ci][1][dx] = v[ci][2][dx];
            v[ci][2][dx] = xs[(ci * 96 + r0 + kh + 2) * 96 + q0 + dx];
          }
        }
      }
#pragma unroll
      for (int kw = 0; kw < 7; kw++) {
#pragma unroll
        for (int ci = 0; ci < 3; ci++) {
          const float w = wp[ci * 49 + kh * 7 + kw];
#pragma unroll
          for (int dy = 0; dy < 3; dy++)
#pragma unroll
            for (int dx = 0; dx < 3; dx++)
              acc[dy * 3 + dx] = fmaf(v[ci][dy][kw + dx], w, acc[dy * 3 + dx]);
        }
      }
    }

    const int c = cg * 8 + c_l;
    const float bias = b1[c];
    float p[9];
#pragma unroll
    for (int j = 0; j < 9; j++) {
      float pre = (acc[j] + bias) / 0.04f;
      p[j] = 1.0f / (1.0f + expf(-pre));
    }
    const uint32_t base = (((uint32_t)(b * 96 + c)) * 900u + (uint32_t)pos) * 9u;
    g_h1[((b * 30 + hb) * 30 + wb) * 96 + c] = pool9(p, k0, k1, base);
  }
}

// ---------------- Layer 2 ----------------
// grid (64, 4, 8): (batch, pooled-row pair, group of 24 out-channels).
// 384 threads = 24 c2 x 16 positions (2 pooled rows x 8 cols).
// Order per output: kh{ kw{ c{ fma } } } with c via float4 chunks (c ascending).
__global__ void __launch_bounds__(384) l2_kernel(const float *__restrict__ b2,
                                                 float *__restrict__ out,
                                                 uint32_t k0, uint32_t k1) {
  extern __shared__ float hs[];  // [12 rows][30 cols][CP]
  const int b = blockIdx.x, rp = blockIdx.y, cg = blockIdx.z;
  const int tid = threadIdx.x;

  // Stage 12 input rows (NHWC, contiguous 34560 floats) into padded smem.
  {
    const float *src = g_h1 + (size_t)(b * 30 + rp * 6) * 30 * 96;
    for (int i = tid; i < 34560 / 4; i += 384) {
      float4 d = ((const float4 *)src)[i];
      int e = i * 4;
      int c = e % 96;
      int rc = e / 96;   // row*30 + col
      *(float4 *)&hs[rc * CP + c] = d;
    }
  }
  __syncthreads();

  const int c2l = tid >> 4;          // 0..23
  const int pos = tid & 15;
  const int hl = pos >> 3, wb = pos & 7;
  const int c2 = cg * 24 + c2l;
  const int hb = rp * 2 + hl;
  const int lr0 = hl * 3, q0 = wb * 3;

  float acc[9];
#pragma unroll
  for (int j = 0; j < 9; j++) acc[j] = 0.0f;

  const float *wbase = g_w2t + (size_t)c2 * 96;

  for (int kk = 0; kk < 49; kk++) {
    const int kh = kk / 7, kw = kk - kh * 7;
    const float *wr = wbase + (size_t)kk * (192 * 96);
    const float *h0 = hs + (lr0 + kh) * (30 * CP) + (q0 + kw) * CP;
#pragma unroll
    for (int c4 = 0; c4 < 24; c4++) {
      const float4 w4 = __ldg((const float4 *)(wr + c4 * 4));
      float4 vv[3][3];
#pragma unroll
      for (int dy = 0; dy < 3; dy++)
#pragma unroll
        for (int dx = 0; dx < 3; dx++)
          vv[dy][dx] = *(const float4 *)(h0 + (dy * 30 + dx) * CP + c4 * 4);
      // c ascending: .x, .y, .z, .w; 9 independent chains inside
#pragma unroll
      for (int dy = 0; dy < 3; dy++)
#pragma unroll
        for (int dx = 0; dx < 3; dx++)
          acc[dy * 3 + dx] = fmaf(vv[dy][dx].x, w4.x, acc[dy * 3 + dx]);
#pragma unroll
      for (int dy = 0; dy < 3; dy++)
#pragma unroll
        for (int dx = 0; dx < 3; dx++)
          acc[dy * 3 + dx] = fmaf(vv[dy][dx].y, w4.y, acc[dy * 3 + dx]);
#pragma unroll
      for (int dy = 0; dy < 3; dy++)
#pragma unroll
        for (int dx = 0; dx < 3; dx++)
          acc[dy * 3 + dx] = fmaf(vv[dy][dx].z, w4.z, acc[dy * 3 + dx]);
#pragma unroll
      for (int dy = 0; dy < 3; dy++)
#pragma unroll
        for (int dx = 0; dx < 3; dx++)
          acc[dy * 3 + dx] = fmaf(vv[dy][dx].w, w4.w, acc[dy * 3 + dx]);
    }
  }

  const float bias = b2[c2];
  float p[9];
#pragma unroll
  for (int j = 0; j < 9; j++) {
    float pre = (acc[j] + bias) / 0.04f;
    p[j] = 1.0f / (1.0f + expf(-pre));
  }
  const uint32_t oidx = (((uint32_t)b * 192u + (uint32_t)c2) * 8u + (uint32_t)hb) * 8u + (uint32_t)wb;
  out[oidx] = pool9(p, k0, k1, oidx * 9u);
}

// ---------------- Launch ----------------
extern "C" void kernel_launch(void *const *d_in, const int *in_sizes, int n_in,
                              void *d_out, int out_size) {
  const float *x  = (const float *)d_in[0];
  const float *w1 = (const float *)d_in[1];
  const float *b1 = (const float *)d_in[2];
  const float *w2 = (const float *)d_in[3];
  const float *b2 = (const float *)d_in[4];

  // key(42) -> (0,42); partitionable fold-like split: kp_i = threefry(key, (0, i))
  uint32_t kp1_0, kp1_1, kp2_0, kp2_1;
  tf2x32(0u, 42u, 0u, 0u, kp1_0, kp1_1);
  tf2x32(0u, 42u, 0u, 1u, kp2_0, kp2_1);

  const int l1_smem = (27648 + 1176) * 4;        // 115296 B
  const int l2_smem = 12 * 30 * CP * 4;          // 144000 B
  cudaFuncSetAttribute(l1_kernel, cudaFuncAttributeMaxDynamicSharedMemorySize, l1_smem);
  cudaFuncSetAttribute(l2_kernel, cudaFuncAttributeMaxDynamicSharedMemorySize, l2_smem);

  w2t_kernel<<<49 * 192 * 96 / 256, 256>>>(w2);
  l1_kernel<<<dim3(64, 12), 256, l1_smem>>>(x, w1, b1, kp1_0, kp1_1);
  l2_kernel<<<dim3(64, 4, 8), 384, l2_smem>>>(b2, (float *)d_out, kp2_0, kp2_1);
}

// round 4
// speedup vs baseline: 1.8614x; 1.8614x over previous
#include <cuda_runtime.h>
#include <cstdint>
#include <math.h>

// ConvDBN: 2-layer conv RBM + stochastic multinomial pooling.
// Accumulation per output is a strict sequential fp32 FMA chain in
// k = (kh, kw, c_in) ascending order (bit-matches XLA:CPU Eigen conv).
// f32x2 packed FMA pairs two *independent* output-channel chains per lane-pair;
// each lane is still an exact fp32 chain in the required order.

#define CP 100  // padded channel stride for L2 smem window (conflict-free: 12k mod 32)

typedef unsigned long long u64;

__device__ float g_h1[64 * 30 * 30 * 96];     // h1 NHWC: [b][h][w][c]
__device__ float g_w2p[49 * 96 * 96 * 2];     // W2 pair-interleaved: [kk][c2pair][c][2]

// ---------------- f32x2 helpers ----------------
__device__ __forceinline__ void ffma2(u64 &d, u64 a, u64 b) {
  asm("fma.rn.f32x2 %0, %1, %2, %0;" : "+l"(d) : "l"(a), "l"(b));
}
__device__ __forceinline__ u64 splat2(float v) {
  u64 r;
  asm("mov.b64 %0, {%1, %1};" : "=l"(r) : "r"(__float_as_uint(v)));
  return r;
}
__device__ __forceinline__ float lane0(u64 a) { return __uint_as_float((uint32_t)a); }
__device__ __forceinline__ float lane1(u64 a) { return __uint_as_float((uint32_t)(a >> 32)); }

// ---------------- Threefry-2x32 (JAX partitionable) ----------------
__host__ __device__ __forceinline__ void tf2x32(uint32_t k0, uint32_t k1,
                                                uint32_t x0, uint32_t x1,
                                                uint32_t &o0, uint32_t &o1) {
  uint32_t ks2 = k0 ^ k1 ^ 0x1BD11BDAu;
  x0 += k0; x1 += k1;
#define TF_RND(r) { x0 += x1; x1 = (x1 << (r)) | (x1 >> (32 - (r))); x1 ^= x0; }
  TF_RND(13) TF_RND(15) TF_RND(26) TF_RND(6)
  x0 += k1;  x1 += ks2 + 1u;
  TF_RND(17) TF_RND(29) TF_RND(16) TF_RND(24)
  x0 += ks2; x1 += k0 + 2u;
  TF_RND(13) TF_RND(15) TF_RND(26) TF_RND(6)
  x0 += k0;  x1 += k1 + 3u;
  TF_RND(17) TF_RND(29) TF_RND(16) TF_RND(24)
  x0 += k1;  x1 += ks2 + 4u;
  TF_RND(13) TF_RND(15) TF_RND(26) TF_RND(6)
  x0 += ks2; x1 += k0 + 5u;
#undef TF_RND
  o0 = x0; o1 = x1;
}

__device__ __forceinline__ float gumbel_at(uint32_t k0, uint32_t k1, uint32_t idx) {
  uint32_t o0, o1;
  tf2x32(k0, k1, 0u, idx, o0, o1);
  uint32_t bits = o0 ^ o1;
  float f = __uint_as_float((bits >> 9) | 0x3F800000u) - 1.0f;
  const float tiny = 1.1754943508222875e-38f;
  f = fmaxf(tiny, f + tiny);
  return -logf(-logf(f));
}

__device__ __forceinline__ float pool9(const float p[9], uint32_t k0, uint32_t k1,
                                       uint32_t base) {
  float best = -1e30f;
  int win = 0;
#pragma unroll
  for (int j = 0; j < 9; j++) {
    float m = logf(p[j] + 1e-8f) + gumbel_at(k0, k1, base + (uint32_t)j);
    if (m > best) { best = m; win = j; }
  }
  return p[win];
}

// ---------------- W2 prep: [c2][c][kh][kw] -> [kk][pp][c][2] ----------------
__global__ void w2p_kernel(const float *__restrict__ w2) {
  int idx = blockIdx.x * 256 + threadIdx.x;   // 49*96*96*2 = 1,806,336 exact
  int s = idx & 1;
  int t = idx >> 1;
  int c = t % 96;
  int u = t / 96;
  int pp = u % 96;
  int kk = u / 96;
  g_w2p[idx] = w2[((pp * 2 + s) * 96 + c) * 49 + kk];
}

// ---------------- Layer 1 ----------------
// grid (64, 6): (batch, 16-channel group). 384 threads.
// Thread: 4 out-channels (2 f32x2 pairs) x one pool cell (9 conv outputs).
__global__ void __launch_bounds__(384) l1_kernel(const float *__restrict__ x,
                                                 const float *__restrict__ w1,
                                                 const float *__restrict__ b1,
                                                 uint32_t k0, uint32_t k1) {
  extern __shared__ float sm[];
  float *xs = sm;                        // 3*96*96 = 27648 floats
  u64 *ws2 = (u64 *)(sm + 27648);        // 8 pairs x 147 taps, pair-interleaved
  const int b = blockIdx.x, cg = blockIdx.y;
  const int cbase = cg * 16;

  const float *xb = x + (size_t)b * 27648;
  for (int i = threadIdx.x; i < 27648 / 4; i += 384)
    ((float4 *)xs)[i] = ((const float4 *)xb)[i];
  for (int i = threadIdx.x; i < 8 * 147; i += 384) {
    int pr = i / 147, m = i - pr * 147;
    float a = w1[(cbase + pr * 2 + 0) * 147 + m];
    float bb = w1[(cbase + pr * 2 + 1) * 147 + m];
    ws2[i] = (u64)__float_as_uint(a) | ((u64)__float_as_uint(bb) << 32);
  }
  __syncthreads();

  for (int item = threadIdx.x; item < 3600; item += 384) {
    const int q = item / 900, pos = item - q * 900;
    const int hb = pos / 30, wb = pos - hb * 30;
    const int r0 = hb * 3, q0 = wb * 3;
    const u64 *wp0 = ws2 + (q * 2 + 0) * 147;
    const u64 *wp1 = ws2 + (q * 2 + 1) * 147;

    u64 acc0[9], acc1[9];
#pragma unroll
    for (int j = 0; j < 9; j++) { acc0[j] = 0ull; acc1[j] = 0ull; }
    float v[3][3][9];  // [ci][row(dy)][col]

#pragma unroll
    for (int kh = 0; kh < 7; kh++) {
#pragma unroll
      for (int ci = 0; ci < 3; ci++) {
        if (kh == 0) {
#pragma unroll
          for (int dy = 0; dy < 3; dy++)
#pragma unroll
            for (int dx = 0; dx < 9; dx++)
              v[ci][dy][dx] = xs[(ci * 96 + r0 + dy) * 96 + q0 + dx];
        } else {
#pragma unroll
          for (int dx = 0; dx < 9; dx++) {
            v[ci][0][dx] = v[ci][1][dx];
            v[ci][1][dx] = v[ci][2][dx];
            v[ci][2][dx] = xs[(ci * 96 + r0 + kh + 2) * 96 + q0 + dx];
          }
        }
      }
#pragma unroll
      for (int kw = 0; kw < 7; kw++) {
#pragma unroll
        for (int ci = 0; ci < 3; ci++) {
          const u64 wA = wp0[ci * 49 + kh * 7 + kw];
          const u64 wB = wp1[ci * 49 + kh * 7 + kw];
#pragma unroll
          for (int dy = 0; dy < 3; dy++)
#pragma unroll
            for (int dx = 0; dx < 3; dx++) {
              const u64 vs = splat2(v[ci][dy][kw + dx]);
              ffma2(acc0[dy * 3 + dx], vs, wA);
              ffma2(acc1[dy * 3 + dx], vs, wB);
            }
        }
      }
    }

    // Epilogue: 4 channels
#pragma unroll
    for (int k4 = 0; k4 < 4; k4++) {
      const int c = cbase + q * 4 + k4;
      float accs[9];
#pragma unroll
      for (int j = 0; j < 9; j++) {
        u64 a = (k4 < 2) ? acc0[j] : acc1[j];
        accs[j] = (k4 & 1) ? lane1(a) : lane0(a);
      }
      const float bias = b1[c];
      float p[9];
#pragma unroll
      for (int j = 0; j < 9; j++) {
        float pre = (accs[j] + bias) / 0.04f;
        p[j] = 1.0f / (1.0f + expf(-pre));
      }
      const uint32_t base = (((uint32_t)(b * 96 + c)) * 900u + (uint32_t)pos) * 9u;
      g_h1[((b * 30 + hb) * 30 + wb) * 96 + c] = pool9(p, k0, k1, base);
    }
  }
}

// ---------------- Layer 2 ----------------
// grid (64, 8): (batch, pooled row hb). 384 threads = 48 c2-quads x 8 wb.
// Thread: 4 out-channels (2 f32x2 pairs) x one pool cell (9 conv outputs).
__global__ void __launch_bounds__(384) l2_kernel(const float *__restrict__ b2,
                                                 float *__restrict__ out,
                                                 uint32_t k0, uint32_t k1) {
  extern __shared__ float hs[];  // [9 rows][30 cols][CP]
  const int b = blockIdx.x, hb = blockIdx.y;
  const int tid = threadIdx.x;

  // Stage 9 NHWC rows (contiguous 25920 floats) into padded smem.
  {
    const float *src = g_h1 + (size_t)(b * 30 + hb * 3) * 30 * 96;
    for (int i = tid; i < 25920 / 4; i += 384) {
      float4 d = ((const float4 *)src)[i];
      int e = i * 4;
      int c = e % 96;
      int rc = e / 96;
      *(float4 *)&hs[rc * CP + c] = d;
    }
  }
  __syncthreads();

  const int c2q = tid >> 3;         // 0..47
  const int wb = tid & 7;
  const int q0 = wb * 3;

  u64 acc0[9], acc1[9];
#pragma unroll
  for (int j = 0; j < 9; j++) { acc0[j] = 0ull; acc1[j] = 0ull; }

  const u64 *wpair = (const u64 *)g_w2p;  // [kk][pp][c] as u64

  for (int kk = 0; kk < 49; kk++) {
    const int kh = kk / 7, kw = kk - kh * 7;
    const u64 *w0u = wpair + ((size_t)kk * 96 + c2q * 2 + 0) * 96;
    const u64 *w1u = w0u + 96;
    const float *hrow = hs + (kh * 30 + q0 + kw) * CP;
#pragma unroll 4
    for (int c4 = 0; c4 < 24; c4++) {
      float4 vv[9];
#pragma unroll
      for (int dy = 0; dy < 3; dy++)
#pragma unroll
        for (int dx = 0; dx < 3; dx++)
          vv[dy * 3 + dx] = *(const float4 *)(hrow + (dy * 30 + dx) * CP + c4 * 4);
      ulonglong2 a01 = ((const ulonglong2 *)(w0u + c4 * 4))[0];
      ulonglong2 a23 = ((const ulonglong2 *)(w0u + c4 * 4))[1];
      ulonglong2 b01 = ((const ulonglong2 *)(w1u + c4 * 4))[0];
      ulonglong2 b23 = ((const ulonglong2 *)(w1u + c4 * 4))[1];
      u64 wA[4] = {a01.x, a01.y, a23.x, a23.y};
      u64 wB[4] = {b01.x, b01.y, b23.x, b23.y};
#pragma unroll
      for (int cc = 0; cc < 4; cc++) {
#pragma unroll
        for (int j = 0; j < 9; j++) {
          const u64 vs = splat2(((const float *)&vv[j])[cc]);
          ffma2(acc0[j], vs, wA[cc]);
          ffma2(acc1[j], vs, wB[cc]);
        }
      }
    }
  }

  // Epilogue: 4 channels
#pragma unroll
  for (int k4 = 0; k4 < 4; k4++) {
    const int c2 = c2q * 4 + k4;
    float accs[9];
#pragma unroll
    for (int j = 0; j < 9; j++) {
      u64 a = (k4 < 2) ? acc0[j] : acc1[j];
      accs[j] = (k4 & 1) ? lane1(a) : lane0(a);
    }
    const float bias = b2[c2];
    float p[9];
#pragma unroll
    for (int j = 0; j < 9; j++) {
      float pre = (accs[j] + bias) / 0.04f;
      p[j] = 1.0f / (1.0f + expf(-pre));
    }
    const uint32_t oidx =
        (((uint32_t)b * 192u + (uint32_t)c2) * 8u + (uint32_t)hb) * 8u + (uint32_t)wb;
    out[oidx] = pool9(p, k0, k1, oidx * 9u);
  }
}

// ---------------- Launch ----------------
extern "C" void kernel_launch(void *const *d_in, const int *in_sizes, int n_in,
                              void *d_out, int out_size) {
  const float *x  = (const float *)d_in[0];
  const float *w1 = (const float *)d_in[1];
  const float *b1 = (const float *)d_in[2];
  const float *w2 = (const float *)d_in[3];
  const float *b2 = (const float *)d_in[4];

  // key(42) -> (0,42); partitionable fold-like split: kp_i = threefry(key, (0, i))
  uint32_t kp1_0, kp1_1, kp2_0, kp2_1;
  tf2x32(0u, 42u, 0u, 0u, kp1_0, kp1_1);
  tf2x32(0u, 42u, 0u, 1u, kp2_0, kp2_1);

  const int l1_smem = (27648 + 8 * 147 * 2) * 4;   // 120,000 B
  const int l2_smem = 9 * 30 * CP * 4;             // 108,000 B
  cudaFuncSetAttribute(l1_kernel, cudaFuncAttributeMaxDynamicSharedMemorySize, l1_smem);
  cudaFuncSetAttribute(l2_kernel, cudaFuncAttributeMaxDynamicSharedMemorySize, l2_smem);

  w2p_kernel<<<49 * 96 * 96 * 2 / 256, 256>>>(w2);
  l1_kernel<<<dim3(64, 6), 384, l1_smem>>>(x, w1, b1, kp1_0, kp1_1);
  l2_kernel<<<dim3(64, 8), 384, l2_smem>>>(b2, (float *)d_out, kp2_0, kp2_1);
}